// round 6
// baseline (speedup 1.0000x reference)
#include <cuda_runtime.h>
#include <math.h>

#define NP 8192

__device__ float g_xt[NP * 64];
__device__ float g_sq[NP];

// smem (~164 KB):
//  As [kq][row]        stride 65 f4 : a-frag broadcast; STS 4kq distinct
//  Bs [kq][(j&7)*16+(j>>3)] stride 129 f4: b-frag 4kq+4tj distinct; writer 4kq
//  Cs [buf][r*132 + col]: writer STS.128 2-way; reader scalar 4-way (cold path)
struct KSmem {
    float4 As[16 * 65];                 // 16.6 KB
    float4 Bs[2][16 * 129];             // 66.0 KB
    float  Cs[2][64 * 132];             // 67.6 KB
    float  sqi[64];
    float  sqj[2][128];
    unsigned long long stop[16][64];    // 8 KB  [slot][row]
    float  slg[16][64];                 // 4 KB
};

__device__ __forceinline__ unsigned fenc(float f) {
    unsigned u = __float_as_uint(f);
    return (u & 0x80000000u) ? ~u : (u | 0x80000000u);
}
__device__ __forceinline__ float fdec(unsigned k) {
    return (k & 0x80000000u) ? __uint_as_float(k ^ 0x80000000u)
                             : __uint_as_float(~k);
}
__device__ __forceinline__ unsigned smaddr(const void* p) {
    unsigned a;
    asm("{ .reg .u64 t; cvta.to.shared.u64 t, %1; cvt.u32.u64 %0, t; }"
        : "=r"(a) : "l"(p));
    return a;
}
__device__ __forceinline__ void cpa16(unsigned dst, const void* src) {
    asm volatile("cp.async.ca.shared.global [%0], [%1], 16;" :: "r"(dst), "l"(src));
}
__device__ __forceinline__ void cpa4(unsigned dst, const void* src) {
    asm volatile("cp.async.ca.shared.global [%0], [%1], 4;" :: "r"(dst), "l"(src));
}
__device__ __forceinline__ void cpcommit() { asm volatile("cp.async.commit_group;"); }
__device__ __forceinline__ void cpwait0()  { asm volatile("cp.async.wait_group 0;" ::: "memory"); }
__device__ __forceinline__ void bar_sync(int id, int cnt) {
    asm volatile("bar.sync %0, %1;" :: "r"(id), "r"(cnt) : "memory");
}
__device__ __forceinline__ void bar_arrive(int id, int cnt) {
    asm volatile("bar.arrive %0, %1;" :: "r"(id), "r"(cnt) : "memory");
}

__global__ void __launch_bounds__(256, 1) k_embed(
        const float* __restrict__ X, const float* __restrict__ W,
        const float* __restrict__ b, float* __restrict__ out) {
    __shared__ float s_acc[256];
    int tid = threadIdx.x;
    int row = (blockIdx.x << 2) + (tid >> 6);
    int col = tid & 63;
    const float* xr = X + (size_t)row * 128;
    float acc = 0.f;
    #pragma unroll 16
    for (int k = 0; k < 128; ++k)
        acc = fmaf(__ldg(xr + k), __ldg(W + k * 64 + col), acc);
    acc = __fadd_rn(acc, __ldg(b + col));
    g_xt[row * 64 + col] = acc;
    out[row * 64 + col] = acc;
    s_acc[tid] = acc;
    __syncthreads();
    if (tid < 128) {
        int sub = tid >> 5, lane = tid & 31;
        float a = s_acc[sub * 64 + lane];
        float c = s_acc[sub * 64 + 32 + lane];
        float v = a * a + c * c;
        #pragma unroll
        for (int o = 16; o; o >>= 1) v += __shfl_xor_sync(0xffffffffu, v, o);
        if (!lane) g_sq[(blockIdx.x << 2) + sub] = v;
    }
}

__device__ __forceinline__ void fill_b(KSmem& sm, int buf, int jb, int tid) {
    #pragma unroll
    for (int it = 0; it < 8; ++it) {
        int f = it * 256 + tid;
        int j = f >> 4, kq = f & 15;
        unsigned dst = smaddr(&sm.Bs[buf][kq * 129 + (j & 7) * 16 + (j >> 3)]);
        cpa16(dst, &g_xt[(size_t)(jb + j) * 64 + kq * 4]);
    }
    if (tid < 128) cpa4(smaddr(&sm.sqj[buf][tid]), &g_sq[jb + tid]);
    cpcommit();
}

// barriers: FULL(buf) = 1+buf (GEMM arrives, sel syncs), count 320
//           FREE(buf) = 3+buf (sel arrives, GEMM syncs), count 320
//           GEMM-internal = 5, count 256
__global__ void __launch_bounds__(320, 1) k_knn(
        const float* __restrict__ q, const float* __restrict__ tparam,
        float* __restrict__ out) {
    extern __shared__ char smraw[];
    KSmem& sm = *reinterpret_cast<KSmem*>(smraw);
    const int tid = threadIdx.x;
    const int ibase = blockIdx.x * 64;
    const float scale = expf(fminf(fmaxf(tparam[0], -5.f), 5.f));
    const float INFF = __int_as_float(0x7f800000);

    if (tid < 256) {
        fill_b(sm, 0, 0, tid);
        #pragma unroll
        for (int qd = 0; qd < 4; ++qd) {
            int f = qd * 256 + tid;
            int r = f >> 4, kq = f & 15;
            sm.As[kq * 65 + r] = *(const float4*)&g_xt[(size_t)(ibase + r) * 64 + kq * 4];
        }
        if (tid < 64) sm.sqi[tid] = g_sq[ibase + tid];
        cpwait0();
    }
    __syncthreads();

    if (tid < 256) {
        // ================= GEMM producer warps =================
        const int ti = tid >> 4, tj = tid & 15;
        float sqiu[4];
        #pragma unroll
        for (int u = 0; u < 4; ++u) sqiu[u] = sm.sqi[ti * 4 + u];

        for (int chunk = 0; chunk < 64; ++chunk) {
            const int cur = chunk & 1, nxt = cur ^ 1;
            const int jn = chunk * 128 + 128;
            if (jn < NP) fill_b(sm, nxt, jn, tid);

            float acc[4][8];
            #pragma unroll
            for (int u = 0; u < 4; ++u)
                #pragma unroll
                for (int c = 0; c < 8; ++c) acc[u][c] = 0.f;

            const float4* B4 = sm.Bs[cur];
            #pragma unroll 4
            for (int kq = 0; kq < 16; ++kq) {
                float4 af[4];
                #pragma unroll
                for (int u = 0; u < 4; ++u) af[u] = sm.As[kq * 65 + ti * 4 + u];
                #pragma unroll
                for (int c = 0; c < 8; ++c) {
                    float4 bf = B4[kq * 129 + c * 16 + tj];
                    #pragma unroll
                    for (int u = 0; u < 4; ++u) {
                        float a0 = acc[u][c];
                        a0 = fmaf(af[u].x, bf.x, a0);
                        a0 = fmaf(af[u].y, bf.y, a0);
                        a0 = fmaf(af[u].z, bf.z, a0);
                        a0 = fmaf(af[u].w, bf.w, a0);
                        acc[u][c] = a0;
                    }
                }
            }

            // wait until selection is done with this Cs buffer (chunk-2)
            if (chunk >= 2) bar_sync(3 + cur, 320);

            // epilogue: logits -> Cs[cur]
            float sqjv[8];
            #pragma unroll
            for (int c = 0; c < 8; ++c) sqjv[c] = sm.sqj[cur][tj * 8 + c];
            #pragma unroll
            for (int u = 0; u < 4; ++u) {
                float* crow = &sm.Cs[cur][(ti * 4 + u) * 132];
                #pragma unroll
                for (int v4 = 0; v4 < 2; ++v4) {
                    float lg[4];
                    #pragma unroll
                    for (int v = 0; v < 4; ++v) {
                        float d = __fadd_rn(__fadd_rn(sqiu[u], sqjv[v4 * 4 + v]),
                                            -__fmul_rn(2.0f, acc[u][v4 * 4 + v]));
                        lg[v] = __fmul_rn(fmaxf(d, 0.0f), scale);
                    }
                    *(float4*)&crow[tj * 8 + v4 * 4] =
                        make_float4(lg[0], lg[1], lg[2], lg[3]);
                }
            }
            __threadfence_block();
            bar_arrive(1 + cur, 320);   // publish FULL(cur)

            cpwait0();
            bar_sync(5, 256);           // Bs[nxt] staged, all producers done reading Bs[cur]
        }
    } else {
        // ================= selection consumer warps (1 thread per row) =================
        const int r = tid - 256;
        const float* qrow = q + (size_t)(ibase + r) * NP;
        float th = INFF;
        int cnt = 0;

        for (int chunk = 0; chunk < 64; ++chunk) {
            const int cur = chunk & 1;
            const int jbase = chunk * 128;
            bar_sync(1 + cur, 320);     // wait FULL(cur)
            const float* crow = &sm.Cs[cur][r * 132];
            #pragma unroll 4
            for (int m = 0; m < 128; ++m) {
                float lgt = crow[m];
                if (lgt - 17.0f <= th) {   // gumbel in [-2.92, 16.7] -> exact bound
                    int j = jbase + m;
                    float qv = __ldg(qrow + j);
                    float pert = __fadd_rn(lgt, logf(-logf(qv)));
                    unsigned long long key =
                        ((unsigned long long)fenc(pert) << 32) | (unsigned)j;
                    if (cnt < 16) {
                        int p2 = cnt;
                        while (p2 > 0 && sm.stop[p2 - 1][r] > key) {
                            sm.stop[p2][r] = sm.stop[p2 - 1][r];
                            sm.slg[p2][r]  = sm.slg[p2 - 1][r];
                            --p2;
                        }
                        sm.stop[p2][r] = key; sm.slg[p2][r] = lgt;
                        if (++cnt == 16) th = fdec((unsigned)(sm.stop[15][r] >> 32));
                    } else if (key < sm.stop[15][r]) {
                        int p2 = 15;
                        while (p2 > 0 && sm.stop[p2 - 1][r] > key) {
                            sm.stop[p2][r] = sm.stop[p2 - 1][r];
                            sm.slg[p2][r]  = sm.slg[p2 - 1][r];
                            --p2;
                        }
                        sm.stop[p2][r] = key; sm.slg[p2][r] = lgt;
                        th = fdec((unsigned)(sm.stop[15][r] >> 32));
                    }
                }
            }
            bar_arrive(3 + cur, 320);   // release FREE(cur)
        }

        // outputs: per-row list is already the exact sorted top-16
        int i = ibase + r;
        #pragma unroll
        for (int s = 0; s < 16; ++s) {
            unsigned long long k64 = sm.stop[s][r];
            int j = (int)(k64 & 0xFFFFu);
            out[524288 + i * 16 + s] = (float)j;
            out[655360 + i * 16 + s] = (float)i;
            out[786432 + i * 16 + s] = -sm.slg[s][r];
        }
    }
}

extern "C" void kernel_launch(void* const* d_in, const int* in_sizes, int n_in,
                              void* d_out, int out_size) {
    const float* X = (const float*)d_in[0];
    const float* W = (const float*)d_in[1];
    const float* b = (const float*)d_in[2];
    const float* t = (const float*)d_in[3];
    const float* q = (const float*)d_in[4];
    float* out = (float*)d_out;

    k_embed<<<2048, 256>>>(X, W, b, out);
    int smem = (int)sizeof(KSmem);
    cudaFuncSetAttribute(k_knn, cudaFuncAttributeMaxDynamicSharedMemorySize, smem);
    k_knn<<<128, 320, smem>>>(q, t, out);
}